// round 1
// baseline (speedup 1.0000x reference)
#include <cuda_runtime.h>
#include <math.h>

#define B_ 4
#define L_ 4096
#define D_ 512
#define M_ (B_*L_)      // 16384 rows total

// ---------------- scratch (device globals: no runtime allocation) ----------
__device__ float g_Q[(size_t)M_ * D_];   // 32 MB
__device__ float g_K[(size_t)M_ * D_];   // 32 MB
__device__ float g_colw[B_ * L_];        // col_w[b,k]
__device__ float g_t[B_ * D_];           // t[b,j] = sum_k col_w[b,k] x[b,k,j]

// ---------------- init ------------------------------------------------------
__global__ void zero_kernel() {
    int tid = blockIdx.x * blockDim.x + threadIdx.x;   // 16384 threads
    g_colw[tid] = 0.f;
    if (tid < B_ * D_) g_t[tid] = 0.f;
}

// ---------------- projection GEMM: C[M,512] = A[M,512] @ W[512,512]^T -------
// 128x128 tile, BK=16, 256 threads, 8x8 micro-tile.
__global__ __launch_bounds__(256, 2)
void gemm_nt(const float* __restrict__ A, const float* __restrict__ W,
             float* __restrict__ C) {
    const int BK = 16;
    const int PAD = 132;                       // k-major rows padded (16B-aligned)
    __shared__ __align__(16) float As[16 * 132];
    __shared__ __align__(16) float Bs[16 * 132];

    const int tid = threadIdx.x;
    const int m00 = blockIdx.y * 128;
    const int n00 = blockIdx.x * 128;
    const int tx = tid & 15, ty = tid >> 4;    // 16x16 thread grid
    const int c4 = tid & 3;                    // float4 column within BK
    const int lrow = tid >> 2;                 // 0..63

    float acc[8][8];
#pragma unroll
    for (int i = 0; i < 8; i++)
#pragma unroll
        for (int j = 0; j < 8; j++) acc[i][j] = 0.f;

    for (int kc = 0; kc < D_; kc += BK) {
        __syncthreads();
#pragma unroll
        for (int i = 0; i < 2; i++) {
            int row = lrow + i * 64;
            float4 va = *(const float4*)(A + (size_t)(m00 + row) * D_ + kc + c4 * 4);
            float4 vb = *(const float4*)(W + (size_t)(n00 + row) * D_ + kc + c4 * 4);
            As[(c4 * 4 + 0) * PAD + row] = va.x;
            As[(c4 * 4 + 1) * PAD + row] = va.y;
            As[(c4 * 4 + 2) * PAD + row] = va.z;
            As[(c4 * 4 + 3) * PAD + row] = va.w;
            Bs[(c4 * 4 + 0) * PAD + row] = vb.x;
            Bs[(c4 * 4 + 1) * PAD + row] = vb.y;
            Bs[(c4 * 4 + 2) * PAD + row] = vb.z;
            Bs[(c4 * 4 + 3) * PAD + row] = vb.w;
        }
        __syncthreads();
#pragma unroll
        for (int kk = 0; kk < BK; kk++) {
            float a[8], b[8];
            *(float4*)&a[0] = *(const float4*)&As[kk * PAD + ty * 8];
            *(float4*)&a[4] = *(const float4*)&As[kk * PAD + ty * 8 + 4];
            *(float4*)&b[0] = *(const float4*)&Bs[kk * PAD + tx * 8];
            *(float4*)&b[4] = *(const float4*)&Bs[kk * PAD + tx * 8 + 4];
#pragma unroll
            for (int i = 0; i < 8; i++)
#pragma unroll
                for (int j = 0; j < 8; j++) acc[i][j] += a[i] * b[j];
        }
    }

#pragma unroll
    for (int i = 0; i < 8; i++) {
        float4 v0 = make_float4(acc[i][0], acc[i][1], acc[i][2], acc[i][3]);
        float4 v1 = make_float4(acc[i][4], acc[i][5], acc[i][6], acc[i][7]);
        float* cp = C + (size_t)(m00 + ty * 8 + i) * D_ + n00 + tx * 8;
        *(float4*)cp = v0;
        *(float4*)(cp + 4) = v1;
    }
}

// ---------------- fused scores + batch-softmax + masked q-reduction --------
// Block: 256 threads = 4 groups (one per batch) x 64 threads.
// Each group computes a 64x64 tile of S_b = Q_b @ K_b^T with 8x8 micro-tiles.
// Then all 4 S tiles go to smem; softmax over b per (q,k); masked sum over q
// accumulates into col_w[b,k] via atomicAdd.
#define SC_KC   16
#define SC_PAD  68                      // 64 + 4, multiple of 4 floats
#define SC_MAIN (B_ * 2 * SC_KC * SC_PAD)          // floats for Qs/Ks of 4 groups
#define SC_SSM  (B_ * 64 * 64)                     // floats for S exchange
#define SC_SMEM ((SC_MAIN + SC_SSM) * 4)           // bytes = 100352

__global__ __launch_bounds__(256, 2)
void scores_kernel(const float* __restrict__ Q, const float* __restrict__ K,
                   const int* __restrict__ lens, float* __restrict__ colw) {
    extern __shared__ __align__(16) float sm[];
    const int tid = threadIdx.x;
    const int g = tid >> 6;           // batch 0..3
    const int thr = tid & 63;
    const int tx = thr & 7, ty = thr >> 3;
    const int q0 = blockIdx.y * 64;
    const int k0 = blockIdx.x * 64;

    float* Qs = sm + g * (2 * SC_KC * SC_PAD);
    float* Ks = Qs + SC_KC * SC_PAD;
    float* Ssm = sm + SC_MAIN;

    const float* Qg = Q + (size_t)g * L_ * D_;
    const float* Kg = K + (size_t)g * L_ * D_;

    float acc[8][8];
#pragma unroll
    for (int i = 0; i < 8; i++)
#pragma unroll
        for (int j = 0; j < 8; j++) acc[i][j] = 0.f;

    const int c4 = thr & 3;
    const int lrow = thr >> 2;        // 0..15

    for (int kc = 0; kc < D_; kc += SC_KC) {
        __syncthreads();
#pragma unroll
        for (int i = 0; i < 4; i++) {
            int row = lrow + i * 16;
            float4 va = *(const float4*)(Qg + (size_t)(q0 + row) * D_ + kc + c4 * 4);
            float4 vb = *(const float4*)(Kg + (size_t)(k0 + row) * D_ + kc + c4 * 4);
            Qs[(c4 * 4 + 0) * SC_PAD + row] = va.x;
            Qs[(c4 * 4 + 1) * SC_PAD + row] = va.y;
            Qs[(c4 * 4 + 2) * SC_PAD + row] = va.z;
            Qs[(c4 * 4 + 3) * SC_PAD + row] = va.w;
            Ks[(c4 * 4 + 0) * SC_PAD + row] = vb.x;
            Ks[(c4 * 4 + 1) * SC_PAD + row] = vb.y;
            Ks[(c4 * 4 + 2) * SC_PAD + row] = vb.z;
            Ks[(c4 * 4 + 3) * SC_PAD + row] = vb.w;
        }
        __syncthreads();
#pragma unroll
        for (int kk = 0; kk < SC_KC; kk++) {
            float a[8], b[8];
            *(float4*)&a[0] = *(const float4*)&Qs[kk * SC_PAD + ty * 8];
            *(float4*)&a[4] = *(const float4*)&Qs[kk * SC_PAD + ty * 8 + 4];
            *(float4*)&b[0] = *(const float4*)&Ks[kk * SC_PAD + tx * 8];
            *(float4*)&b[4] = *(const float4*)&Ks[kk * SC_PAD + tx * 8 + 4];
#pragma unroll
            for (int i = 0; i < 8; i++)
#pragma unroll
                for (int j = 0; j < 8; j++) acc[i][j] += a[i] * b[j];
        }
    }

    __syncthreads();
    // park S tiles in smem: Ssm[g][q_local][k_local]
#pragma unroll
    for (int i = 0; i < 8; i++)
#pragma unroll
        for (int j = 0; j < 8; j++)
            Ssm[g * 4096 + (ty * 8 + i) * 64 + (tx * 8 + j)] = acc[i][j];
    __syncthreads();

    // batch softmax + masked q-sum
    const int kloc = tid & 63;
    const int qb = (tid >> 6) * 16;
    const int le0 = lens[0], le1 = lens[1], le2 = lens[2], le3 = lens[3];
    float a0 = 0.f, a1 = 0.f, a2 = 0.f, a3 = 0.f;
#pragma unroll 4
    for (int qq = 0; qq < 16; qq++) {
        int q = qb + qq;
        float s0 = Ssm[0 * 4096 + q * 64 + kloc];
        float s1 = Ssm[1 * 4096 + q * 64 + kloc];
        float s2 = Ssm[2 * 4096 + q * 64 + kloc];
        float s3 = Ssm[3 * 4096 + q * 64 + kloc];
        float m = fmaxf(fmaxf(s0, s1), fmaxf(s2, s3));
        float e0 = __expf((s0 - m) * 0.0625f);   // scale = 1/sqrt(256)
        float e1 = __expf((s1 - m) * 0.0625f);
        float e2 = __expf((s2 - m) * 0.0625f);
        float e3 = __expf((s3 - m) * 0.0625f);
        float inv = 1.f / (e0 + e1 + e2 + e3);
        int qg = q0 + q;
        if (qg < le0) a0 += e0 * inv;
        if (qg < le1) a1 += e1 * inv;
        if (qg < le2) a2 += e2 * inv;
        if (qg < le3) a3 += e3 * inv;
    }
    int kg = k0 + kloc;
    atomicAdd(&colw[0 * L_ + kg], a0);
    atomicAdd(&colw[1 * L_ + kg], a1);
    atomicAdd(&colw[2 * L_ + kg], a2);
    atomicAdd(&colw[3 * L_ + kg], a3);
}

// ---------------- t[b,j] = sum_k col_w[b,k] * x[b,k,j] ----------------------
__global__ void colw_x_kernel(const float* __restrict__ x) {
    int b = blockIdx.x;                 // 0..3
    int ks = blockIdx.y * 128;          // 32 slices of 128 k's
    int j = threadIdx.x;                // 0..511
    const float* xb = x + ((size_t)b * L_ + ks) * D_;
    const float* cw = g_colw + b * L_ + ks;
    float s = 0.f;
#pragma unroll 4
    for (int kk = 0; kk < 128; kk++)
        s += cw[kk] * xb[(size_t)kk * D_ + j];
    atomicAdd(&g_t[b * D_ + j], s);
}

// ---------------- out[b,d] = sum_j Wv[d,j] * t[b,j] -------------------------
__global__ void final_kernel(const float* __restrict__ Wv, float* __restrict__ out) {
    int warp = (blockIdx.x * blockDim.x + threadIdx.x) >> 5;   // 0..2047
    int lane = threadIdx.x & 31;
    int b = warp >> 9;
    int d = warp & 511;
    const float* wr = Wv + (size_t)d * D_;
    const float* tr = g_t + b * D_;
    float s = 0.f;
    for (int j = lane; j < D_; j += 32) s += wr[j] * tr[j];
#pragma unroll
    for (int o = 16; o; o >>= 1) s += __shfl_down_sync(0xffffffffu, s, o);
    if (lane == 0) out[b * D_ + d] = s;
}

// ---------------- launch -----------------------------------------------------
extern "C" void kernel_launch(void* const* d_in, const int* in_sizes, int n_in,
                              void* d_out, int out_size) {
    const float* x   = (const float*)d_in[0];
    const float* Wq  = (const float*)d_in[1];
    const float* Wk  = (const float*)d_in[2];
    const float* Wv  = (const float*)d_in[3];
    const int*  lens = (const int*)d_in[4];
    float* out = (float*)d_out;

    float *Qp, *Kp, *cwp;
    cudaGetSymbolAddress((void**)&Qp, g_Q);
    cudaGetSymbolAddress((void**)&Kp, g_K);
    cudaGetSymbolAddress((void**)&cwp, g_colw);

    zero_kernel<<<64, 256>>>();

    dim3 gg(4, 128);                      // N/128 x M/128
    gemm_nt<<<gg, 256>>>(x, Wq, Qp);
    gemm_nt<<<gg, 256>>>(x, Wk, Kp);

    cudaFuncSetAttribute(scores_kernel,
                         cudaFuncAttributeMaxDynamicSharedMemorySize, SC_SMEM);
    dim3 gs(64, 64);                      // k-tiles x q-tiles
    scores_kernel<<<gs, 256, SC_SMEM>>>(Qp, Kp, lens, cwp);

    colw_x_kernel<<<dim3(4, 32), 512>>>(x);
    final_kernel<<<256, 256>>>(Wv, out);
}

// round 3
// speedup vs baseline: 5.7308x; 5.7308x over previous
#include <cuda_runtime.h>
#include <cuda_fp16.h>
#include <stdint.h>

#define B_ 4
#define L_ 4096
#define D_ 512
#define M_ (B_*L_)

// ---------------- device scratch ---------------------------------------------
__device__ __half g_x16[(size_t)M_*D_];
__device__ __half g_Wq16[D_*D_], g_Wk16[D_*D_];
__device__ __half g_Q[(size_t)M_*D_], g_K[(size_t)M_*D_];
__device__ float g_colw[B_*L_];
__device__ float g_t[B_*D_];

// ---------------- helpers ----------------------------------------------------
#define SWZ(o) ((o) ^ ((((uint32_t)(o))>>3)&0x70u))

__device__ __forceinline__ uint32_t smem_u32(const void* p){
    return (uint32_t)__cvta_generic_to_shared(p);
}
__device__ __forceinline__ void ldsm4(uint32_t* r, uint32_t a){
    asm volatile("ldmatrix.sync.aligned.m8n8.x4.shared.b16 {%0,%1,%2,%3}, [%4];"
        : "=r"(r[0]), "=r"(r[1]), "=r"(r[2]), "=r"(r[3]) : "r"(a));
}
__device__ __forceinline__ void mma16816(float* d, const uint32_t* a, uint32_t b0, uint32_t b1){
    asm volatile("mma.sync.aligned.m16n8k16.row.col.f32.f16.f16.f32 "
        "{%0,%1,%2,%3}, {%4,%5,%6,%7}, {%8,%9}, {%0,%1,%2,%3};"
        : "+f"(d[0]), "+f"(d[1]), "+f"(d[2]), "+f"(d[3])
        : "r"(a[0]), "r"(a[1]), "r"(a[2]), "r"(a[3]), "r"(b0), "r"(b1));
}
__device__ __forceinline__ void cpa16(uint32_t s, const void* g){
    asm volatile("cp.async.cg.shared.global [%0], [%1], 16;" :: "r"(s), "l"(g) : "memory");
}
#define CP_COMMIT() asm volatile("cp.async.commit_group;" ::: "memory")
#define CP_WAIT(n)  asm volatile("cp.async.wait_group %0;" :: "n"(n) : "memory")

// ---------------- small kernels ----------------------------------------------
__global__ void zero_kernel(){
    int tid = blockIdx.x*blockDim.x + threadIdx.x;
    g_colw[tid] = 0.f;
    if (tid < B_*D_) g_t[tid] = 0.f;
}

__global__ void tohalf_kernel(const float* __restrict__ s, __half* __restrict__ d, int n4){
    int i = blockIdx.x*blockDim.x + threadIdx.x;
    if (i >= n4) return;
    float4 v = ((const float4*)s)[i];
    __half2 h0 = __floats2half2_rn(v.x, v.y);
    __half2 h1 = __floats2half2_rn(v.z, v.w);
    ((__half2*)d)[i*2]   = h0;
    ((__half2*)d)[i*2+1] = h1;
}

// ---------------- projection GEMM (HMMA): C = A @ W^T, fp16 in/out, f32 acc ---
// Block tile 128m x 128n, K-chunks of 64, double-buffered cp.async.
#define PJ_STAGE 32768
#define PJ_SMEM  (2*PJ_STAGE)

__device__ __forceinline__ void pj_load(const __half* __restrict__ A,
                                        const __half* __restrict__ W,
                                        int m0, int n0, int kc, uint32_t sdst, int tid){
#pragma unroll
    for (int i = 0; i < 8; i++){
        int lin = i*256 + tid;               // 0..2047
        int sub = lin >> 9, row = (lin >> 3) & 63, sec = lin & 7;
        const __half* src;
        if (sub < 2) src = A + (size_t)(m0 + sub*64 + row)*D_ + kc + sec*8;
        else         src = W + (size_t)(n0 + (sub-2)*64 + row)*D_ + kc + sec*8;
        cpa16(sdst + sub*8192 + SWZ(row*128 + sec*16), src);
    }
}

__global__ __launch_bounds__(256, 1)
void proj_hmma(const __half* __restrict__ A, const __half* __restrict__ W,
               __half* __restrict__ C){
    extern __shared__ __align__(1024) char sm[];
    const int tid = threadIdx.x, wid = tid >> 5, lane = tid & 31;
    const int m0 = blockIdx.y * 128, n0 = blockIdx.x * 128;
    const uint32_t sb = smem_u32(sm);

    const int mw = (wid & 3) * 32, nw = (wid >> 2) * 64;
    const int a_r = lane & 15, a_s = (lane >> 4) * 16;
    const int b_n = (lane & 7) + ((lane >> 4) << 3);
    const int b_s = ((lane >> 3) & 1) * 16;

    float acc[2][8][4];
#pragma unroll
    for (int i = 0; i < 2; i++)
#pragma unroll
        for (int j = 0; j < 8; j++)
#pragma unroll
            for (int v = 0; v < 4; v++) acc[i][j][v] = 0.f;

    pj_load(A, W, m0, n0, 0, sb, tid); CP_COMMIT();

    for (int c = 0; c < 8; c++){
        if (c < 7){ pj_load(A, W, m0, n0, (c+1)*64, sb + ((c+1)&1)*PJ_STAGE, tid);
                    CP_COMMIT(); CP_WAIT(1); }
        else      { CP_WAIT(0); }
        __syncthreads();
        uint32_t st = sb + (c & 1) * PJ_STAGE;
#pragma unroll
        for (int ks = 0; ks < 4; ks++){
            int kb = ks * 32;
            uint32_t A0[4], A1[4], Bv[4];
            {
                int r0 = mw + a_r, r1 = mw + 16 + a_r;
                ldsm4(A0, st + (r0 >> 6)*8192 + SWZ((r0 & 63)*128 + kb + a_s));
                ldsm4(A1, st + (r1 >> 6)*8192 + SWZ((r1 & 63)*128 + kb + a_s));
            }
#pragma unroll
            for (int nb = 0; nb < 4; nb++){
                int n = nw + nb*16 + b_n;
                ldsm4(Bv, st + (2 + (n >> 6))*8192 + SWZ((n & 63)*128 + kb + b_s));
                mma16816(acc[0][nb*2],   A0, Bv[0], Bv[1]);
                mma16816(acc[0][nb*2+1], A0, Bv[2], Bv[3]);
                mma16816(acc[1][nb*2],   A1, Bv[0], Bv[1]);
                mma16816(acc[1][nb*2+1], A1, Bv[2], Bv[3]);
            }
        }
        __syncthreads();
    }

    const int er = lane >> 2, ec = (lane & 3) * 2;
#pragma unroll
    for (int mt = 0; mt < 2; mt++)
#pragma unroll
        for (int n8 = 0; n8 < 8; n8++){
            size_t r = (size_t)(m0 + mw + mt*16 + er);
            int col = n0 + nw + n8*8 + ec;
            *(__half2*)&C[r*D_ + col] =
                __floats2half2_rn(acc[mt][n8][0], acc[mt][n8][1]);
            *(__half2*)&C[(r+8)*D_ + col] =
                __floats2half2_rn(acc[mt][n8][2], acc[mt][n8][3]);
        }
}

// ---------------- fused scores (HMMA) + batch softmax + masked q-reduction ---
// Block tile: 128q x 64k for ALL 4 batches. 8 warps: warp = (batch, q-half).
// Stage: Q 4b x 128rows (8 subtiles) + K 4b x 64rows (4 subtiles) = 96KB.
#define SC_STAGE 98304
#define SC_SMEM  (2*SC_STAGE)

__device__ __forceinline__ void sc_load(const __half* __restrict__ Q,
                                        const __half* __restrict__ K,
                                        int q0, int k0, int kc, uint32_t sdst, int tid){
#pragma unroll
    for (int i = 0; i < 24; i++){
        int lin = i*256 + tid;               // 0..6143
        int sub = lin >> 9, row = (lin >> 3) & 63, sec = lin & 7;
        const __half* src;
        if (sub < 8){
            int b = sub >> 1;
            src = Q + (size_t)(b*L_ + q0 + (sub & 1)*64 + row)*D_ + kc + sec*8;
        } else {
            int b = sub - 8;
            src = K + (size_t)(b*L_ + k0 + row)*D_ + kc + sec*8;
        }
        cpa16(sdst + sub*8192 + SWZ(row*128 + sec*16), src);
    }
}

__global__ __launch_bounds__(256, 1)
void scores_hmma(const __half* __restrict__ Q, const __half* __restrict__ K,
                 const int* __restrict__ lens, float* __restrict__ colw){
    extern __shared__ __align__(1024) char sm[];
    const int tid = threadIdx.x, wid = tid >> 5, lane = tid & 31;
    const int q0 = blockIdx.y * 128, k0 = blockIdx.x * 64;
    const uint32_t sb = smem_u32(sm);

    const int b   = wid >> 1;                 // batch
    const int qsub = b*2 + (wid & 1);         // this warp's Q subtile (64 rows)
    const int ksub = 8 + b;
    const int a_r = lane & 15, a_s = (lane >> 4) * 16;
    const int b_n = (lane & 7) + ((lane >> 4) << 3);
    const int b_s = ((lane >> 3) & 1) * 16;

    float acc[4][8][4];
#pragma unroll
    for (int i = 0; i < 4; i++)
#pragma unroll
        for (int j = 0; j < 8; j++)
#pragma unroll
            for (int v = 0; v < 4; v++) acc[i][j][v] = 0.f;

    sc_load(Q, K, q0, k0, 0, sb, tid); CP_COMMIT();

    for (int c = 0; c < 8; c++){
        if (c < 7){ sc_load(Q, K, q0, k0, (c+1)*64, sb + ((c+1)&1)*SC_STAGE, tid);
                    CP_COMMIT(); CP_WAIT(1); }
        else      { CP_WAIT(0); }
        __syncthreads();
        uint32_t qt = sb + (c & 1)*SC_STAGE + qsub*8192;
        uint32_t kt = sb + (c & 1)*SC_STAGE + ksub*8192;
#pragma unroll
        for (int ks = 0; ks < 4; ks++){
            int kb = ks * 32;
            uint32_t Af[4][4], Bv[4];
#pragma unroll
            for (int mt = 0; mt < 4; mt++)
                ldsm4(Af[mt], qt + SWZ((mt*16 + a_r)*128 + kb + a_s));
#pragma unroll
            for (int nb = 0; nb < 4; nb++){
                ldsm4(Bv, kt + SWZ((nb*16 + b_n)*128 + kb + b_s));
#pragma unroll
                for (int mt = 0; mt < 4; mt++){
                    mma16816(acc[mt][nb*2],   Af[mt], Bv[0], Bv[1]);
                    mma16816(acc[mt][nb*2+1], Af[mt], Bv[2], Bv[3]);
                }
            }
        }
        __syncthreads();
    }

    // park S into smem: Ssm[b][q(128)][k(64)]
    float* Ssm = (float*)sm;
    const int er = lane >> 2, ec = (lane & 3) * 2;
    const int qh = (wid & 1) * 64;
#pragma unroll
    for (int mt = 0; mt < 4; mt++)
#pragma unroll
        for (int n8 = 0; n8 < 8; n8++){
            int r = qh + mt*16 + er;
            int kk = n8*8 + ec;
            *(float2*)&Ssm[(size_t)b*8192 + (size_t)r*64 + kk] =
                make_float2(acc[mt][n8][0], acc[mt][n8][1]);
            *(float2*)&Ssm[(size_t)b*8192 + (size_t)(r+8)*64 + kk] =
                make_float2(acc[mt][n8][2], acc[mt][n8][3]);
        }
    __syncthreads();

    // batch softmax + masked q reduction
    const int kloc = tid & 63;
    const int qb = (tid >> 6) * 32;
    const int le0 = lens[0], le1 = lens[1], le2 = lens[2], le3 = lens[3];
    float a0 = 0.f, a1 = 0.f, a2 = 0.f, a3 = 0.f;
#pragma unroll 4
    for (int qq = 0; qq < 32; qq++){
        int q = qb + qq;
        float s0 = Ssm[0*8192 + q*64 + kloc];
        float s1 = Ssm[1*8192 + q*64 + kloc];
        float s2 = Ssm[2*8192 + q*64 + kloc];
        float s3 = Ssm[3*8192 + q*64 + kloc];
        float mx = fmaxf(fmaxf(s0, s1), fmaxf(s2, s3));
        float e0 = __expf((s0 - mx) * 0.0625f);
        float e1 = __expf((s1 - mx) * 0.0625f);
        float e2 = __expf((s2 - mx) * 0.0625f);
        float e3 = __expf((s3 - mx) * 0.0625f);
        float inv = 1.f / (e0 + e1 + e2 + e3);
        int qg = q0 + q;
        if (qg < le0) a0 += e0 * inv;
        if (qg < le1) a1 += e1 * inv;
        if (qg < le2) a2 += e2 * inv;
        if (qg < le3) a3 += e3 * inv;
    }
    int kg = k0 + kloc;
    atomicAdd(&colw[0*L_ + kg], a0);
    atomicAdd(&colw[1*L_ + kg], a1);
    atomicAdd(&colw[2*L_ + kg], a2);
    atomicAdd(&colw[3*L_ + kg], a3);
}

// ---------------- tail kernels ------------------------------------------------
__global__ void colw_x_kernel(const float* __restrict__ x){
    int b = blockIdx.x;
    int ks = blockIdx.y * 128;
    int j = threadIdx.x;
    const float* xb = x + ((size_t)b * L_ + ks) * D_;
    const float* cw = g_colw + b * L_ + ks;
    float s = 0.f;
#pragma unroll 4
    for (int kk = 0; kk < 128; kk++)
        s += cw[kk] * xb[(size_t)kk * D_ + j];
    atomicAdd(&g_t[b * D_ + j], s);
}

__global__ void final_kernel(const float* __restrict__ Wv, float* __restrict__ out){
    int warp = (blockIdx.x * blockDim.x + threadIdx.x) >> 5;
    int lane = threadIdx.x & 31;
    int b = warp >> 9;
    int d = warp & 511;
    const float* wr = Wv + (size_t)d * D_;
    const float* tr = g_t + b * D_;
    float s = 0.f;
    for (int j = lane; j < D_; j += 32) s += wr[j] * tr[j];
#pragma unroll
    for (int o = 16; o; o >>= 1) s += __shfl_down_sync(0xffffffffu, s, o);
    if (lane == 0) out[b * D_ + d] = s;
}

// ---------------- launch -------------------------------------------------------
extern "C" void kernel_launch(void* const* d_in, const int* in_sizes, int n_in,
                              void* d_out, int out_size){
    const float* x   = (const float*)d_in[0];
    const float* Wq  = (const float*)d_in[1];
    const float* Wk  = (const float*)d_in[2];
    const float* Wv  = (const float*)d_in[3];
    const int*  lens = (const int*)d_in[4];
    float* out = (float*)d_out;

    __half *x16, *wq16, *wk16, *qp, *kp;
    float *cwp;
    cudaGetSymbolAddress((void**)&x16,  g_x16);
    cudaGetSymbolAddress((void**)&wq16, g_Wq16);
    cudaGetSymbolAddress((void**)&wk16, g_Wk16);
    cudaGetSymbolAddress((void**)&qp,   g_Q);
    cudaGetSymbolAddress((void**)&kp,   g_K);
    cudaGetSymbolAddress((void**)&cwp,  g_colw);

    cudaFuncSetAttribute(proj_hmma,   cudaFuncAttributeMaxDynamicSharedMemorySize, PJ_SMEM);
    cudaFuncSetAttribute(scores_hmma, cudaFuncAttributeMaxDynamicSharedMemorySize, SC_SMEM);

    zero_kernel<<<64, 256>>>();

    int n4x = (int)((size_t)M_ * D_ / 4);
    tohalf_kernel<<<(n4x + 255) / 256, 256>>>(x, x16, n4x);
    int n4w = D_ * D_ / 4;
    tohalf_kernel<<<(n4w + 255) / 256, 256>>>(Wq, wq16, n4w);
    tohalf_kernel<<<(n4w + 255) / 256, 256>>>(Wk, wk16, n4w);

    proj_hmma<<<dim3(4, 128), 256, PJ_SMEM>>>(x16, wq16, qp);
    proj_hmma<<<dim3(4, 128), 256, PJ_SMEM>>>(x16, wk16, kp);

    scores_hmma<<<dim3(64, 32), 256, SC_SMEM>>>(qp, kp, lens, cwp);

    colw_x_kernel<<<dim3(4, 32), 512>>>(x);
    final_kernel<<<256, 256>>>(Wv, out);
}

// round 4
// speedup vs baseline: 6.1443x; 1.0721x over previous
#include <cuda_runtime.h>
#include <cuda_fp16.h>
#include <stdint.h>

#define B_ 4
#define L_ 4096
#define D_ 512
#define M_ (B_*L_)

// ---------------- device scratch ---------------------------------------------
__device__ __half g_x16[(size_t)M_*D_];
__device__ __half g_Wq16[D_*D_], g_Wk16[D_*D_];
__device__ __half g_Q[(size_t)M_*D_], g_K[(size_t)M_*D_];
__device__ float g_colw[B_*L_];
__device__ float g_t[B_*D_];

// ---------------- helpers ----------------------------------------------------
#define SWZ(o) ((o) ^ ((((uint32_t)(o))>>3)&0x70u))

__device__ __forceinline__ uint32_t smem_u32(const void* p){
    return (uint32_t)__cvta_generic_to_shared(p);
}
__device__ __forceinline__ void ldsm4(uint32_t* r, uint32_t a){
    asm volatile("ldmatrix.sync.aligned.m8n8.x4.shared.b16 {%0,%1,%2,%3}, [%4];"
        : "=r"(r[0]), "=r"(r[1]), "=r"(r[2]), "=r"(r[3]) : "r"(a));
}
__device__ __forceinline__ void mma16816(float* d, const uint32_t* a, uint32_t b0, uint32_t b1){
    asm volatile("mma.sync.aligned.m16n8k16.row.col.f32.f16.f16.f32 "
        "{%0,%1,%2,%3}, {%4,%5,%6,%7}, {%8,%9}, {%0,%1,%2,%3};"
        : "+f"(d[0]), "+f"(d[1]), "+f"(d[2]), "+f"(d[3])
        : "r"(a[0]), "r"(a[1]), "r"(a[2]), "r"(a[3]), "r"(b0), "r"(b1));
}
__device__ __forceinline__ void cpa16(uint32_t s, const void* g){
    asm volatile("cp.async.cg.shared.global [%0], [%1], 16;" :: "r"(s), "l"(g) : "memory");
}
#define CP_COMMIT() asm volatile("cp.async.commit_group;" ::: "memory")
#define CP_WAIT(n)  asm volatile("cp.async.wait_group %0;" :: "n"(n) : "memory")

// ---------------- prep kernels -------------------------------------------------
__global__ void tohalf_kernel(const float* __restrict__ s, __half* __restrict__ d, int n4){
    int i = blockIdx.x*blockDim.x + threadIdx.x;
    if (i >= n4) return;
    float4 v = ((const float4*)s)[i];
    ((__half2*)d)[i*2]   = __floats2half2_rn(v.x, v.y);
    ((__half2*)d)[i*2+1] = __floats2half2_rn(v.z, v.w);
}

// converts both weight matrices and zeroes accumulators (one launch)
__global__ void prep_w_kernel(const float* __restrict__ Wq, const float* __restrict__ Wk){
    int i = blockIdx.x*blockDim.x + threadIdx.x;   // 65536 threads
    float4 a = ((const float4*)Wq)[i];
    float4 b = ((const float4*)Wk)[i];
    ((__half2*)g_Wq16)[i*2]   = __floats2half2_rn(a.x, a.y);
    ((__half2*)g_Wq16)[i*2+1] = __floats2half2_rn(a.z, a.w);
    ((__half2*)g_Wk16)[i*2]   = __floats2half2_rn(b.x, b.y);
    ((__half2*)g_Wk16)[i*2+1] = __floats2half2_rn(b.z, b.w);
    if (i < B_*L_) g_colw[i] = 0.f;
    if (i < B_*D_) g_t[i] = 0.f;
}

// ---------------- projection GEMM (HMMA): C = A @ W^T --------------------------
#define PJ_STAGE 32768
#define PJ_SMEM  (2*PJ_STAGE)

__device__ __forceinline__ void pj_load(const __half* __restrict__ A,
                                        const __half* __restrict__ W,
                                        int m0, int n0, int kc, uint32_t sdst, int tid){
#pragma unroll
    for (int i = 0; i < 8; i++){
        int lin = i*256 + tid;
        int sub = lin >> 9, row = (lin >> 3) & 63, sec = lin & 7;
        const __half* src;
        if (sub < 2) src = A + (size_t)(m0 + sub*64 + row)*D_ + kc + sec*8;
        else         src = W + (size_t)(n0 + (sub-2)*64 + row)*D_ + kc + sec*8;
        cpa16(sdst + sub*8192 + SWZ(row*128 + sec*16), src);
    }
}

__global__ __launch_bounds__(256, 1)
void proj_hmma(const __half* __restrict__ A,
               const __half* __restrict__ W0, const __half* __restrict__ W1,
               __half* __restrict__ C0, __half* __restrict__ C1){
    extern __shared__ __align__(1024) char sm[];
    const __half* W = blockIdx.z ? W1 : W0;
    __half* C = blockIdx.z ? C1 : C0;
    const int tid = threadIdx.x, wid = tid >> 5, lane = tid & 31;
    const int m0 = blockIdx.y * 128, n0 = blockIdx.x * 128;
    const uint32_t sb = smem_u32(sm);

    const int mw = (wid & 3) * 32, nw = (wid >> 2) * 64;
    const int a_r = lane & 15, a_s = (lane >> 4) * 16;
    const int b_n = (lane & 7) + ((lane >> 4) << 3);
    const int b_s = ((lane >> 3) & 1) * 16;

    float acc[2][8][4];
#pragma unroll
    for (int i = 0; i < 2; i++)
#pragma unroll
        for (int j = 0; j < 8; j++)
#pragma unroll
            for (int v = 0; v < 4; v++) acc[i][j][v] = 0.f;

    pj_load(A, W, m0, n0, 0, sb, tid); CP_COMMIT();

    for (int c = 0; c < 8; c++){
        if (c < 7){ pj_load(A, W, m0, n0, (c+1)*64, sb + ((c+1)&1)*PJ_STAGE, tid);
                    CP_COMMIT(); CP_WAIT(1); }
        else      { CP_WAIT(0); }
        __syncthreads();
        uint32_t st = sb + (c & 1) * PJ_STAGE;
#pragma unroll
        for (int ks = 0; ks < 4; ks++){
            int kb = ks * 32;
            uint32_t A0[4], A1[4], Bv[4];
            {
                int r0 = mw + a_r, r1 = mw + 16 + a_r;
                ldsm4(A0, st + (r0 >> 6)*8192 + SWZ((r0 & 63)*128 + kb + a_s));
                ldsm4(A1, st + (r1 >> 6)*8192 + SWZ((r1 & 63)*128 + kb + a_s));
            }
#pragma unroll
            for (int nb = 0; nb < 4; nb++){
                int n = nw + nb*16 + b_n;
                ldsm4(Bv, st + (2 + (n >> 6))*8192 + SWZ((n & 63)*128 + kb + b_s));
                mma16816(acc[0][nb*2],   A0, Bv[0], Bv[1]);
                mma16816(acc[0][nb*2+1], A0, Bv[2], Bv[3]);
                mma16816(acc[1][nb*2],   A1, Bv[0], Bv[1]);
                mma16816(acc[1][nb*2+1], A1, Bv[2], Bv[3]);
            }
        }
        __syncthreads();
    }

    const int er = lane >> 2, ec = (lane & 3) * 2;
#pragma unroll
    for (int mt = 0; mt < 2; mt++)
#pragma unroll
        for (int n8 = 0; n8 < 8; n8++){
            size_t r = (size_t)(m0 + mw + mt*16 + er);
            int col = n0 + nw + n8*8 + ec;
            *(__half2*)&C[r*D_ + col] =
                __floats2half2_rn(acc[mt][n8][0], acc[mt][n8][1]);
            *(__half2*)&C[(r+8)*D_ + col] =
                __floats2half2_rn(acc[mt][n8][2], acc[mt][n8][3]);
        }
}

// ---------------- fused scores (HMMA, 512 threads) -----------------------------
// Tile: 128q x 64k x 4 batches. 16 warps: warp = (batch = wid&3, qquarter = wid>>2).
// Stage: Q 8 subtiles + K 4 subtiles of [64 x 64] halfs = 96KB; double-buffered.
#define SC_STAGE 98304
#define SC_SMEM  (2*SC_STAGE)
#define SST      66                       // padded S row stride (floats)
#define SBATCH   (128*SST)                // floats per batch plane (8448)
#define RED_OFF  (4*SBATCH*4)             // byte offset of reduction buffer (135168)

__device__ __forceinline__ void sc_load(const __half* __restrict__ Q,
                                        const __half* __restrict__ K,
                                        int q0, int k0, int kc, uint32_t sdst, int tid){
#pragma unroll
    for (int i = 0; i < 12; i++){
        int lin = i*512 + tid;               // 0..6143
        int sub = lin >> 9, row = (lin >> 3) & 63, sec = lin & 7;
        const __half* src;
        if (sub < 8){
            int b = sub >> 1;
            src = Q + (size_t)(b*L_ + q0 + (sub & 1)*64 + row)*D_ + kc + sec*8;
        } else {
            int b = sub - 8;
            src = K + (size_t)(b*L_ + k0 + row)*D_ + kc + sec*8;
        }
        cpa16(sdst + sub*8192 + SWZ(row*128 + sec*16), src);
    }
}

__global__ __launch_bounds__(512, 1)
void scores_hmma(const __half* __restrict__ Q, const __half* __restrict__ K,
                 const int* __restrict__ lens, float* __restrict__ colw){
    extern __shared__ __align__(1024) char sm[];
    const int tid = threadIdx.x, wid = tid >> 5, lane = tid & 31;
    const int q0 = blockIdx.y * 128, k0 = blockIdx.x * 64;
    const uint32_t sb = smem_u32(sm);

    const int b    = wid & 3;                 // batch
    const int qq4  = wid >> 2;                // q-quarter 0..3 (32 rows each)
    const int qst  = b*2 + (qq4 >> 1);        // Q subtile index
    const int qoff = (qq4 & 1) * 32;          // row offset within subtile
    const int ksub = 8 + b;
    const int a_r = lane & 15, a_s = (lane >> 4) * 16;
    const int b_n = (lane & 7) + ((lane >> 4) << 3);
    const int b_s = ((lane >> 3) & 1) * 16;

    float acc[2][8][4];
#pragma unroll
    for (int i = 0; i < 2; i++)
#pragma unroll
        for (int j = 0; j < 8; j++)
#pragma unroll
            for (int v = 0; v < 4; v++) acc[i][j][v] = 0.f;

    sc_load(Q, K, q0, k0, 0, sb, tid); CP_COMMIT();

    for (int c = 0; c < 8; c++){
        if (c < 7){ sc_load(Q, K, q0, k0, (c+1)*64, sb + ((c+1)&1)*SC_STAGE, tid);
                    CP_COMMIT(); CP_WAIT(1); }
        else      { CP_WAIT(0); }
        __syncthreads();
        uint32_t qt = sb + (c & 1)*SC_STAGE + qst*8192;
        uint32_t kt = sb + (c & 1)*SC_STAGE + ksub*8192;
#pragma unroll
        for (int ks = 0; ks < 4; ks++){
            int kb = ks * 32;
            uint32_t A0[4], A1[4], Bv[4];
            ldsm4(A0, qt + SWZ((qoff      + a_r)*128 + kb + a_s));
            ldsm4(A1, qt + SWZ((qoff + 16 + a_r)*128 + kb + a_s));
#pragma unroll
            for (int nb = 0; nb < 4; nb++){
                ldsm4(Bv, kt + SWZ((nb*16 + b_n)*128 + kb + b_s));
                mma16816(acc[0][nb*2],   A0, Bv[0], Bv[1]);
                mma16816(acc[0][nb*2+1], A0, Bv[2], Bv[3]);
                mma16816(acc[1][nb*2],   A1, Bv[0], Bv[1]);
                mma16816(acc[1][nb*2+1], A1, Bv[2], Bv[3]);
            }
        }
        __syncthreads();
    }

    // park S into padded smem: Ssm[b][q(128)][k(64)] with row stride SST
    float* Ssm = (float*)sm;
    float* red = (float*)(sm + RED_OFF);      // [8 qgroups][64 k][4 b]
    const int er = lane >> 2, ec = (lane & 3) * 2;
#pragma unroll
    for (int mt = 0; mt < 2; mt++)
#pragma unroll
        for (int n8 = 0; n8 < 8; n8++){
            int r = qq4*32 + mt*16 + er;
            int kk = n8*8 + ec;
            *(float2*)&Ssm[(size_t)b*SBATCH + (size_t)r*SST + kk] =
                make_float2(acc[mt][n8][0], acc[mt][n8][1]);
            *(float2*)&Ssm[(size_t)b*SBATCH + (size_t)(r+8)*SST + kk] =
                make_float2(acc[mt][n8][2], acc[mt][n8][3]);
        }
    __syncthreads();

    // batch softmax + masked q reduction (each thread: 16 q's for one k)
    const int kloc = tid & 63;
    const int qg = tid >> 6;                  // 0..7
    const int qb = qg * 16;
    const int le0 = lens[0], le1 = lens[1], le2 = lens[2], le3 = lens[3];
    float a0 = 0.f, a1 = 0.f, a2 = 0.f, a3 = 0.f;
#pragma unroll 4
    for (int qq = 0; qq < 16; qq++){
        int q = qb + qq;
        float s0 = Ssm[0*SBATCH + q*SST + kloc];
        float s1 = Ssm[1*SBATCH + q*SST + kloc];
        float s2 = Ssm[2*SBATCH + q*SST + kloc];
        float s3 = Ssm[3*SBATCH + q*SST + kloc];
        float mx = fmaxf(fmaxf(s0, s1), fmaxf(s2, s3));
        float e0 = __expf((s0 - mx) * 0.0625f);
        float e1 = __expf((s1 - mx) * 0.0625f);
        float e2 = __expf((s2 - mx) * 0.0625f);
        float e3 = __expf((s3 - mx) * 0.0625f);
        float inv = 1.f / (e0 + e1 + e2 + e3);
        int qgl = q0 + q;
        if (qgl < le0) a0 += e0 * inv;
        if (qgl < le1) a1 += e1 * inv;
        if (qgl < le2) a2 += e2 * inv;
        if (qgl < le3) a3 += e3 * inv;
    }
    *(float4*)&red[(qg*64 + kloc)*4] = make_float4(a0, a1, a2, a3);
    __syncthreads();

    if (tid < 256){
        int kl = tid >> 2, bb = tid & 3;
        float s = 0.f;
#pragma unroll
        for (int g = 0; g < 8; g++) s += red[(g*64 + kl)*4 + bb];
        atomicAdd(&colw[bb*L_ + k0 + kl], s);
    }
}

// ---------------- tail kernels --------------------------------------------------
__global__ void colw_x_kernel(){
    int b = blockIdx.x;
    int ks = blockIdx.y * 128;
    int j = threadIdx.x;
    const __half* xb = g_x16 + ((size_t)b * L_ + ks) * D_;
    const float* cw = g_colw + b * L_ + ks;
    float s = 0.f;
#pragma unroll 4
    for (int kk = 0; kk < 128; kk++)
        s += cw[kk] * __half2float(xb[(size_t)kk * D_ + j]);
    atomicAdd(&g_t[b * D_ + j], s);
}

__global__ void final_kernel(const float* __restrict__ Wv, float* __restrict__ out){
    int warp = (blockIdx.x * blockDim.x + threadIdx.x) >> 5;
    int lane = threadIdx.x & 31;
    int b = warp >> 9;
    int d = warp & 511;
    const float* wr = Wv + (size_t)d * D_;
    const float* tr = g_t + b * D_;
    float s = 0.f;
    for (int j = lane; j < D_; j += 32) s += wr[j] * tr[j];
#pragma unroll
    for (int o = 16; o; o >>= 1) s += __shfl_down_sync(0xffffffffu, s, o);
    if (lane == 0) out[b * D_ + d] = s;
}

// ---------------- launch ----------------------------------------------------------
extern "C" void kernel_launch(void* const* d_in, const int* in_sizes, int n_in,
                              void* d_out, int out_size){
    const float* x   = (const float*)d_in[0];
    const float* Wq  = (const float*)d_in[1];
    const float* Wk  = (const float*)d_in[2];
    const float* Wv  = (const float*)d_in[3];
    const int*  lens = (const int*)d_in[4];
    float* out = (float*)d_out;

    __half *x16, *wq16, *wk16, *qp, *kp;
    float *cwp;
    cudaGetSymbolAddress((void**)&x16,  g_x16);
    cudaGetSymbolAddress((void**)&wq16, g_Wq16);
    cudaGetSymbolAddress((void**)&wk16, g_Wk16);
    cudaGetSymbolAddress((void**)&qp,   g_Q);
    cudaGetSymbolAddress((void**)&kp,   g_K);
    cudaGetSymbolAddress((void**)&cwp,  g_colw);

    cudaFuncSetAttribute(proj_hmma,   cudaFuncAttributeMaxDynamicSharedMemorySize, PJ_SMEM);
    cudaFuncSetAttribute(scores_hmma, cudaFuncAttributeMaxDynamicSharedMemorySize, SC_SMEM);

    int n4x = (int)((size_t)M_ * D_ / 4);
    tohalf_kernel<<<(n4x + 255) / 256, 256>>>(x, x16, n4x);
    prep_w_kernel<<<256, 256>>>(Wq, Wk);

    proj_hmma<<<dim3(4, 128, 2), 256, PJ_SMEM>>>(x16, wq16, wk16, qp, kp);

    scores_hmma<<<dim3(64, 32), 512, SC_SMEM>>>(qp, kp, lens, cwp);

    colw_x_kernel<<<dim3(4, 32), 512>>>();
    final_kernel<<<256, 256>>>(Wv, out);
}

// round 5
// speedup vs baseline: 6.1828x; 1.0063x over previous
#include <cuda_runtime.h>
#include <cuda_fp16.h>
#include <stdint.h>

#define B_ 4
#define L_ 4096
#define D_ 512
#define M_ (B_*L_)

// ---------------- device scratch ---------------------------------------------
__device__ __half g_x16[(size_t)M_*D_];
__device__ __half g_Wq16[D_*D_], g_Wk16[D_*D_];
__device__ __half g_Q[(size_t)M_*D_], g_K[(size_t)M_*D_];
__device__ float g_colw[B_*L_];
__device__ float g_t[B_*D_];

// ---------------- helpers ----------------------------------------------------
#define SWZ(o) ((o) ^ ((((uint32_t)(o))>>3)&0x70u))

__device__ __forceinline__ uint32_t smem_u32(const void* p){
    return (uint32_t)__cvta_generic_to_shared(p);
}
__device__ __forceinline__ void ldsm4(uint32_t* r, uint32_t a){
    asm volatile("ldmatrix.sync.aligned.m8n8.x4.shared.b16 {%0,%1,%2,%3}, [%4];"
        : "=r"(r[0]), "=r"(r[1]), "=r"(r[2]), "=r"(r[3]) : "r"(a));
}
// fp32-acc MMA (projections)
__device__ __forceinline__ void mma16816(float* d, const uint32_t* a, uint32_t b0, uint32_t b1){
    asm volatile("mma.sync.aligned.m16n8k16.row.col.f32.f16.f16.f32 "
        "{%0,%1,%2,%3}, {%4,%5,%6,%7}, {%8,%9}, {%0,%1,%2,%3};"
        : "+f"(d[0]), "+f"(d[1]), "+f"(d[2]), "+f"(d[3])
        : "r"(a[0]), "r"(a[1]), "r"(a[2]), "r"(a[3]), "r"(b0), "r"(b1));
}
// fp16-acc MMA (scores)
__device__ __forceinline__ void mma16816h(uint32_t* d, const uint32_t* a, uint32_t b0, uint32_t b1){
    asm volatile("mma.sync.aligned.m16n8k16.row.col.f16.f16.f16.f16 "
        "{%0,%1}, {%2,%3,%4,%5}, {%6,%7}, {%0,%1};"
        : "+r"(d[0]), "+r"(d[1])
        : "r"(a[0]), "r"(a[1]), "r"(a[2]), "r"(a[3]), "r"(b0), "r"(b1));
}
__device__ __forceinline__ void cpa16(uint32_t s, const void* g){
    asm volatile("cp.async.cg.shared.global [%0], [%1], 16;" :: "r"(s), "l"(g) : "memory");
}
#define CP_COMMIT() asm volatile("cp.async.commit_group;" ::: "memory")
#define CP_WAIT(n)  asm volatile("cp.async.wait_group %0;" :: "n"(n) : "memory")

// ---------------- prep kernels -------------------------------------------------
__global__ void tohalf_kernel(const float* __restrict__ s, __half* __restrict__ d, int n4){
    int i = blockIdx.x*blockDim.x + threadIdx.x;
    if (i >= n4) return;
    float4 v = ((const float4*)s)[i];
    ((__half2*)d)[i*2]   = __floats2half2_rn(v.x, v.y);
    ((__half2*)d)[i*2+1] = __floats2half2_rn(v.z, v.w);
}

__global__ void prep_w_kernel(const float* __restrict__ Wq, const float* __restrict__ Wk){
    int i = blockIdx.x*blockDim.x + threadIdx.x;
    float4 a = ((const float4*)Wq)[i];
    float4 b = ((const float4*)Wk)[i];
    ((__half2*)g_Wq16)[i*2]   = __floats2half2_rn(a.x, a.y);
    ((__half2*)g_Wq16)[i*2+1] = __floats2half2_rn(a.z, a.w);
    ((__half2*)g_Wk16)[i*2]   = __floats2half2_rn(b.x, b.y);
    ((__half2*)g_Wk16)[i*2+1] = __floats2half2_rn(b.z, b.w);
    if (i < B_*L_) g_colw[i] = 0.f;
    if (i < B_*D_) g_t[i] = 0.f;
}

// ---------------- projection GEMM (HMMA): C = A @ W^T --------------------------
#define PJ_STAGE 32768
#define PJ_SMEM  (2*PJ_STAGE)

__device__ __forceinline__ void pj_load(const __half* __restrict__ A,
                                        const __half* __restrict__ W,
                                        int m0, int n0, int kc, uint32_t sdst, int tid){
#pragma unroll
    for (int i = 0; i < 8; i++){
        int lin = i*256 + tid;
        int sub = lin >> 9, row = (lin >> 3) & 63, sec = lin & 7;
        const __half* src;
        if (sub < 2) src = A + (size_t)(m0 + sub*64 + row)*D_ + kc + sec*8;
        else         src = W + (size_t)(n0 + (sub-2)*64 + row)*D_ + kc + sec*8;
        cpa16(sdst + sub*8192 + SWZ(row*128 + sec*16), src);
    }
}

__global__ __launch_bounds__(256, 1)
void proj_hmma(const __half* __restrict__ A,
               const __half* __restrict__ W0, const __half* __restrict__ W1,
               __half* __restrict__ C0, __half* __restrict__ C1){
    extern __shared__ __align__(1024) char sm[];
    const __half* W = blockIdx.z ? W1 : W0;
    __half* C = blockIdx.z ? C1 : C0;
    const int tid = threadIdx.x, wid = tid >> 5, lane = tid & 31;
    const int m0 = blockIdx.y * 128, n0 = blockIdx.x * 128;
    const uint32_t sb = smem_u32(sm);

    const int mw = (wid & 3) * 32, nw = (wid >> 2) * 64;
    const int a_r = lane & 15, a_s = (lane >> 4) * 16;
    const int b_n = (lane & 7) + ((lane >> 4) << 3);
    const int b_s = ((lane >> 3) & 1) * 16;

    float acc[2][8][4];
#pragma unroll
    for (int i = 0; i < 2; i++)
#pragma unroll
        for (int j = 0; j < 8; j++)
#pragma unroll
            for (int v = 0; v < 4; v++) acc[i][j][v] = 0.f;

    pj_load(A, W, m0, n0, 0, sb, tid); CP_COMMIT();

    for (int c = 0; c < 8; c++){
        if (c < 7){ pj_load(A, W, m0, n0, (c+1)*64, sb + ((c+1)&1)*PJ_STAGE, tid);
                    CP_COMMIT(); CP_WAIT(1); }
        else      { CP_WAIT(0); }
        __syncthreads();
        uint32_t st = sb + (c & 1) * PJ_STAGE;

        uint32_t Af[2][2][4], Bf[2][4];
        // prime ks=0
        {
            int r0 = mw + a_r, r1 = mw + 16 + a_r;
            ldsm4(Af[0][0], st + (r0 >> 6)*8192 + SWZ((r0 & 63)*128 + a_s));
            ldsm4(Af[0][1], st + (r1 >> 6)*8192 + SWZ((r1 & 63)*128 + a_s));
            int n = nw + b_n;
            ldsm4(Bf[0], st + (2 + (n >> 6))*8192 + SWZ((n & 63)*128 + b_s));
        }
#pragma unroll
        for (int ks = 0; ks < 4; ks++){
            const int ab = ks & 1;
#pragma unroll
            for (int nb = 0; nb < 4; nb++){
                const int bb = nb & 1;
                if (nb < 3){
                    int n = nw + (nb+1)*16 + b_n;
                    ldsm4(Bf[bb^1], st + (2 + (n >> 6))*8192 + SWZ((n & 63)*128 + ks*32 + b_s));
                } else if (ks < 3){
                    int r0 = mw + a_r, r1 = mw + 16 + a_r;
                    ldsm4(Af[ab^1][0], st + (r0 >> 6)*8192 + SWZ((r0 & 63)*128 + (ks+1)*32 + a_s));
                    ldsm4(Af[ab^1][1], st + (r1 >> 6)*8192 + SWZ((r1 & 63)*128 + (ks+1)*32 + a_s));
                    int n = nw + b_n;
                    ldsm4(Bf[bb^1], st + (2 + (n >> 6))*8192 + SWZ((n & 63)*128 + (ks+1)*32 + b_s));
                }
                mma16816(acc[0][nb*2],   Af[ab][0], Bf[bb][0], Bf[bb][1]);
                mma16816(acc[0][nb*2+1], Af[ab][0], Bf[bb][2], Bf[bb][3]);
                mma16816(acc[1][nb*2],   Af[ab][1], Bf[bb][0], Bf[bb][1]);
                mma16816(acc[1][nb*2+1], Af[ab][1], Bf[bb][2], Bf[bb][3]);
            }
        }
        __syncthreads();
    }

    const int er = lane >> 2, ec = (lane & 3) * 2;
#pragma unroll
    for (int mt = 0; mt < 2; mt++)
#pragma unroll
        for (int n8 = 0; n8 < 8; n8++){
            size_t r = (size_t)(m0 + mw + mt*16 + er);
            int col = n0 + nw + n8*8 + ec;
            *(__half2*)&C[r*D_ + col] =
                __floats2half2_rn(acc[mt][n8][0], acc[mt][n8][1]);
            *(__half2*)&C[(r+8)*D_ + col] =
                __floats2half2_rn(acc[mt][n8][2], acc[mt][n8][3]);
        }
}

// ---------------- fused scores (HMMA fp16-acc, 512 threads, pipelined) ---------
#define SC_STAGE 98304
#define SC_SMEM  (2*SC_STAGE)
#define SST      66
#define SBATCH   (128*SST)
#define RED_OFF  (4*SBATCH*4)

__device__ __forceinline__ void sc_load(const __half* __restrict__ Q,
                                        const __half* __restrict__ K,
                                        int q0, int k0, int kc, uint32_t sdst, int tid){
#pragma unroll
    for (int i = 0; i < 12; i++){
        int lin = i*512 + tid;
        int sub = lin >> 9, row = (lin >> 3) & 63, sec = lin & 7;
        const __half* src;
        if (sub < 8){
            int b = sub >> 1;
            src = Q + (size_t)(b*L_ + q0 + (sub & 1)*64 + row)*D_ + kc + sec*8;
        } else {
            int b = sub - 8;
            src = K + (size_t)(b*L_ + k0 + row)*D_ + kc + sec*8;
        }
        cpa16(sdst + sub*8192 + SWZ(row*128 + sec*16), src);
    }
}

__global__ __launch_bounds__(512, 1)
void scores_hmma(const __half* __restrict__ Q, const __half* __restrict__ K,
                 const int* __restrict__ lens, float* __restrict__ colw){
    extern __shared__ __align__(1024) char sm[];
    const int tid = threadIdx.x, wid = tid >> 5, lane = tid & 31;
    const int q0 = blockIdx.y * 128, k0 = blockIdx.x * 64;
    const uint32_t sb = smem_u32(sm);

    const int b    = wid & 3;
    const int qq4  = wid >> 2;
    const int qst  = b*2 + (qq4 >> 1);
    const int qoff = (qq4 & 1) * 32;
    const int ksub = 8 + b;
    const int a_r = lane & 15, a_s = (lane >> 4) * 16;
    const int b_n = (lane & 7) + ((lane >> 4) << 3);
    const int b_s = ((lane >> 3) & 1) * 16;

    uint32_t acc[2][8][2];          // fp16x2 accumulators
#pragma unroll
    for (int i = 0; i < 2; i++)
#pragma unroll
        for (int j = 0; j < 8; j++){ acc[i][j][0] = 0u; acc[i][j][1] = 0u; }

    sc_load(Q, K, q0, k0, 0, sb, tid); CP_COMMIT();

    for (int c = 0; c < 8; c++){
        if (c < 7){ sc_load(Q, K, q0, k0, (c+1)*64, sb + ((c+1)&1)*SC_STAGE, tid);
                    CP_COMMIT(); CP_WAIT(1); }
        else      { CP_WAIT(0); }
        __syncthreads();
        uint32_t qt = sb + (c & 1)*SC_STAGE + qst*8192;
        uint32_t kt = sb + (c & 1)*SC_STAGE + ksub*8192;

        uint32_t Af[2][2][4], Bf[2][4];
        ldsm4(Af[0][0], qt + SWZ((qoff      + a_r)*128 + a_s));
        ldsm4(Af[0][1], qt + SWZ((qoff + 16 + a_r)*128 + a_s));
        ldsm4(Bf[0],    kt + SWZ((b_n)*128 + b_s));
#pragma unroll
        for (int ks = 0; ks < 4; ks++){
            const int ab = ks & 1;
#pragma unroll
            for (int nb = 0; nb < 4; nb++){
                const int bb = nb & 1;
                if (nb < 3){
                    ldsm4(Bf[bb^1], kt + SWZ(((nb+1)*16 + b_n)*128 + ks*32 + b_s));
                } else if (ks < 3){
                    ldsm4(Af[ab^1][0], qt + SWZ((qoff      + a_r)*128 + (ks+1)*32 + a_s));
                    ldsm4(Af[ab^1][1], qt + SWZ((qoff + 16 + a_r)*128 + (ks+1)*32 + a_s));
                    ldsm4(Bf[bb^1],    kt + SWZ((b_n)*128 + (ks+1)*32 + b_s));
                }
                mma16816h(acc[0][nb*2],   Af[ab][0], Bf[bb][0], Bf[bb][1]);
                mma16816h(acc[0][nb*2+1], Af[ab][0], Bf[bb][2], Bf[bb][3]);
                mma16816h(acc[1][nb*2],   Af[ab][1], Bf[bb][0], Bf[bb][1]);
                mma16816h(acc[1][nb*2+1], Af[ab][1], Bf[bb][2], Bf[bb][3]);
            }
        }
        __syncthreads();
    }

    // park S (convert fp16->fp32) into padded smem
    float* Ssm = (float*)sm;
    float* red = (float*)(sm + RED_OFF);
    const int er = lane >> 2, ec = (lane & 3) * 2;
#pragma unroll
    for (int mt = 0; mt < 2; mt++)
#pragma unroll
        for (int n8 = 0; n8 < 8; n8++){
            int r = qq4*32 + mt*16 + er;
            int kk = n8*8 + ec;
            float2 f0 = __half22float2(*(__half2*)&acc[mt][n8][0]);
            float2 f1 = __half22float2(*(__half2*)&acc[mt][n8][1]);
            *(float2*)&Ssm[(size_t)b*SBATCH + (size_t)r*SST + kk] = f0;
            *(float2*)&Ssm[(size_t)b*SBATCH + (size_t)(r+8)*SST + kk] = f1;
        }
    __syncthreads();

    // batch softmax + masked q reduction
    const int kloc = tid & 63;
    const int qg = tid >> 6;
    const int qb = qg * 16;
    const int le0 = lens[0], le1 = lens[1], le2 = lens[2], le3 = lens[3];
    float a0 = 0.f, a1 = 0.f, a2 = 0.f, a3 = 0.f;
#pragma unroll 4
    for (int qq = 0; qq < 16; qq++){
        int q = qb + qq;
        float s0 = Ssm[0*SBATCH + q*SST + kloc];
        float s1 = Ssm[1*SBATCH + q*SST + kloc];
        float s2 = Ssm[2*SBATCH + q*SST + kloc];
        float s3 = Ssm[3*SBATCH + q*SST + kloc];
        float mx = fmaxf(fmaxf(s0, s1), fmaxf(s2, s3));
        float e0 = __expf((s0 - mx) * 0.0625f);
        float e1 = __expf((s1 - mx) * 0.0625f);
        float e2 = __expf((s2 - mx) * 0.0625f);
        float e3 = __expf((s3 - mx) * 0.0625f);
        float inv = 1.f / (e0 + e1 + e2 + e3);
        int qgl = q0 + q;
        if (qgl < le0) a0 += e0 * inv;
        if (qgl < le1) a1 += e1 * inv;
        if (qgl < le2) a2 += e2 * inv;
        if (qgl < le3) a3 += e3 * inv;
    }
    *(float4*)&red[(qg*64 + kloc)*4] = make_float4(a0, a1, a2, a3);
    __syncthreads();

    if (tid < 256){
        int kl = tid >> 2, bb = tid & 3;
        float s = 0.f;
#pragma unroll
        for (int g = 0; g < 8; g++) s += red[(g*64 + kl)*4 + bb];
        atomicAdd(&colw[bb*L_ + k0 + kl], s);
    }
}

// ---------------- tail kernels --------------------------------------------------
__global__ void colw_x_kernel(){
    int b = blockIdx.x;
    int ks = blockIdx.y * 128;
    int j = threadIdx.x;
    const __half* xb = g_x16 + ((size_t)b * L_ + ks) * D_;
    const float* cw = g_colw + b * L_ + ks;
    float s = 0.f;
#pragma unroll 4
    for (int kk = 0; kk < 128; kk++)
        s += cw[kk] * __half2float(xb[(size_t)kk * D_ + j]);
    atomicAdd(&g_t[b * D_ + j], s);
}

__global__ void final_kernel(const float* __restrict__ Wv, float* __restrict__ out){
    int warp = (blockIdx.x * blockDim.x + threadIdx.x) >> 5;
    int lane = threadIdx.x & 31;
    int b = warp >> 9;
    int d = warp & 511;
    const float* wr = Wv + (size_t)d * D_;
    const float* tr = g_t + b * D_;
    float s = 0.f;
    for (int j = lane; j < D_; j += 32) s += wr[j] * tr[j];
#pragma unroll
    for (int o = 16; o; o >>= 1) s += __shfl_down_sync(0xffffffffu, s, o);
    if (lane == 0) out[b * D_ + d] = s;
}

// ---------------- launch ----------------------------------------------------------
extern "C" void kernel_launch(void* const* d_in, const int* in_sizes, int n_in,
                              void* d_out, int out_size){
    const float* x   = (const float*)d_in[0];
    const float* Wq  = (const float*)d_in[1];
    const float* Wk  = (const float*)d_in[2];
    const float* Wv  = (const float*)d_in[3];
    const int*  lens = (const int*)d_in[4];
    float* out = (float*)d_out;

    __half *x16, *wq16, *wk16, *qp, *kp;
    float *cwp;
    cudaGetSymbolAddress((void**)&x16,  g_x16);
    cudaGetSymbolAddress((void**)&wq16, g_Wq16);
    cudaGetSymbolAddress((void**)&wk16, g_Wk16);
    cudaGetSymbolAddress((void**)&qp,   g_Q);
    cudaGetSymbolAddress((void**)&kp,   g_K);
    cudaGetSymbolAddress((void**)&cwp,  g_colw);

    cudaFuncSetAttribute(proj_hmma,   cudaFuncAttributeMaxDynamicSharedMemorySize, PJ_SMEM);
    cudaFuncSetAttribute(scores_hmma, cudaFuncAttributeMaxDynamicSharedMemorySize, SC_SMEM);

    int n4x = (int)((size_t)M_ * D_ / 4);
    tohalf_kernel<<<(n4x + 255) / 256, 256>>>(x, x16, n4x);
    prep_w_kernel<<<256, 256>>>(Wq, Wk);

    proj_hmma<<<dim3(4, 128, 2), 256, PJ_SMEM>>>(x16, wq16, wk16, qp, kp);

    scores_hmma<<<dim3(64, 32), 512, SC_SMEM>>>(qp, kp, lens, cwp);

    colw_x_kernel<<<dim3(4, 32), 512>>>();
    final_kernel<<<256, 256>>>(Wv, out);
}